// round 3
// baseline (speedup 1.0000x reference)
#include <cuda_runtime.h>
#include <cuda_bf16.h>
#include <cstdint>

#define B      32
#define QLEN   32
#define DLEN   1024
#define EMB    300
#define CDIM   128
#define MD     (B*DLEN)   // 32768 doc rows
#define MQ     (B*QLEN)   // 1024 query rows

// ---------------- device scratch (static; no allocations allowed) ----------------
__device__ float g_DE[(MD + 4) * EMB];        // gathered doc embeddings (+4 zero pad rows)
__device__ float g_QE[(MQ + 4) * EMB];        // gathered query embeddings (+4 zero pad rows)
__device__ float g_WT[1800 * CDIM];           // transposed conv weights; rows [0,300)=k1,[300,900)=k2,[900,1800)=k3
__device__ float g_DENC[3ull * MD * CDIM];    // normalized+masked doc encodings per ksize
__device__ float g_QENC[3ull * MQ * CDIM];    // normalized+masked query encodings per ksize
__device__ float g_LOGITS[B * 189];

// ---------------- 1) gather embeddings, zero pad rows ----------------
__global__ void gather_kernel(const int* __restrict__ qids, const int* __restrict__ dids,
                              const float* __restrict__ emb) {
    int gwarp = (blockIdx.x * blockDim.x + threadIdx.x) >> 5;
    int lane  = threadIdx.x & 31;
    if (gwarp < MD) {
        int id = dids[gwarp];
        const float4* src = (const float4*)(emb + (size_t)id * EMB);
        float4* dst = (float4*)(g_DE + (size_t)gwarp * EMB);
        #pragma unroll
        for (int i = 0; i < 3; i++) { int c = lane + i * 32; if (c < 75) dst[c] = src[c]; }
    } else if (gwarp < MD + MQ) {
        int r = gwarp - MD;
        int id = qids[r];
        const float4* src = (const float4*)(emb + (size_t)id * EMB);
        float4* dst = (float4*)(g_QE + (size_t)r * EMB);
        #pragma unroll
        for (int i = 0; i < 3; i++) { int c = lane + i * 32; if (c < 75) dst[c] = src[c]; }
    } else if (gwarp < MD + MQ + 8) {
        int r = gwarp - MD - MQ;
        float4* dst = (r < 4) ? (float4*)(g_DE + (size_t)(MD + r) * EMB)
                              : (float4*)(g_QE + (size_t)(MQ + (r - 4)) * EMB);
        float4 z = make_float4(0.f, 0.f, 0.f, 0.f);
        #pragma unroll
        for (int i = 0; i < 3; i++) { int c = lane + i * 32; if (c < 75) dst[c] = z; }
    }
}

// ---------------- 2) transpose conv weights to [kcol][c] ----------------
// kcol = t*300 + e;  W[kcol][c] = w[c, e, t]   (w layout: [CDIM][EMB][k])
__global__ void wt_kernel(const float* __restrict__ w1, const float* __restrict__ w2,
                          const float* __restrict__ w3) {
    int idx = blockIdx.x * blockDim.x + threadIdx.x;
    if (idx >= 1800 * CDIM) return;
    int kcol_g = idx / CDIM, c = idx % CDIM;
    const float* w; int k, local;
    if (kcol_g < 300)       { w = w1; k = 1; local = kcol_g; }
    else if (kcol_g < 900)  { w = w2; k = 2; local = kcol_g - 300; }
    else                    { w = w3; k = 3; local = kcol_g - 900; }
    int t = local / 300, e = local % 300;
    g_WT[idx] = w[(size_t)c * EMB * k + (size_t)e * k + t];
}

// ---------------- 3) conv GEMM + bias + ReLU + L2-normalize + mask ----------------
// C[m][c] = relu( sum_kcol A[m*300+kcol] * WT[kcol][c] + bias[c] ), then row-L2-normalized, * mask[m]
__global__ __launch_bounds__(256) void conv_gemm_kernel(int is_query,
                                                        const float* __restrict__ bias1,
                                                        const float* __restrict__ bias2,
                                                        const float* __restrict__ bias3,
                                                        const float* __restrict__ masks) {
    __shared__ float As[2][20][132];   // [k][row] transposed A tile
    __shared__ float Bs[2][20][132];   // [k][col]

    const float* Abase = is_query ? g_QE : g_DE;
    float* Cbase       = is_query ? g_QENC : g_DENC;
    const int Mtotal   = is_query ? MQ : MD;

    const int kidx  = blockIdx.y;                 // 0,1,2 -> ksize 1,2,3
    const int Ksize = 300 * (kidx + 1);
    const int koff  = (kidx == 0) ? 0 : (kidx == 1 ? 300 : 900);
    const float* bias = (kidx == 0) ? bias1 : (kidx == 1 ? bias2 : bias3);
    float* C = Cbase + (size_t)kidx * Mtotal * CDIM;

    const int m0  = blockIdx.x * 128;
    const int tid = threadIdx.x;
    const int ty  = tid >> 4, tx = tid & 15;

    float acc[8][8];
    #pragma unroll
    for (int i = 0; i < 8; i++)
        #pragma unroll
        for (int j = 0; j < 8; j++) acc[i][j] = 0.f;

    const int nkt = Ksize / 20;

    // stage loader (A: 128x20 transposed, B: 20x128)
    auto load_stage = [&](int s, int kpos) {
        #pragma unroll
        for (int i = 0; i < 5; i++) {
            int idx = tid + i * 256;                    // 1280 float2
            int r = idx / 10, cc = (idx % 10) * 2;
            float2 v = *(const float2*)(Abase + (size_t)(m0 + r) * EMB + kpos + cc);
            As[s][cc][r]     = v.x;
            As[s][cc + 1][r] = v.y;
        }
        #pragma unroll
        for (int i = 0; i < 5; i++) {
            int idx = tid + i * 256;                    // 1280 float2
            int r = idx / 64, cc = (idx % 64) * 2;
            float2 v = *(const float2*)(g_WT + (size_t)(koff + kpos + r) * CDIM + cc);
            *(float2*)&Bs[s][r][cc] = v;
        }
    };

    load_stage(0, 0);
    __syncthreads();
    int s = 0;
    for (int kt = 0; kt < nkt; kt++) {
        if (kt + 1 < nkt) load_stage(s ^ 1, (kt + 1) * 20);
        #pragma unroll
        for (int kk = 0; kk < 20; kk++) {
            float a[8], bb[8];
            *(float4*)&a[0]  = *(const float4*)&As[s][kk][ty * 8];
            *(float4*)&a[4]  = *(const float4*)&As[s][kk][ty * 8 + 4];
            *(float4*)&bb[0] = *(const float4*)&Bs[s][kk][tx * 8];
            *(float4*)&bb[4] = *(const float4*)&Bs[s][kk][tx * 8 + 4];
            #pragma unroll
            for (int i = 0; i < 8; i++)
                #pragma unroll
                for (int j = 0; j < 8; j++) acc[i][j] = fmaf(a[i], bb[j], acc[i][j]);
        }
        __syncthreads();
        s ^= 1;
    }

    // epilogue: bias + relu + per-row L2 normalize + mask
    float bb[8];
    *(float4*)&bb[0] = *(const float4*)(bias + tx * 8);
    *(float4*)&bb[4] = *(const float4*)(bias + tx * 8 + 4);

    #pragma unroll
    for (int i = 0; i < 8; i++) {
        float ss = 0.f;
        #pragma unroll
        for (int j = 0; j < 8; j++) {
            float v = fmaxf(acc[i][j] + bb[j], 0.f);
            acc[i][j] = v;
            ss = fmaf(v, v, ss);
        }
        // reduce across the 16 lanes (tx) sharing this ty
        #pragma unroll
        for (int off = 1; off < 16; off <<= 1)
            ss += __shfl_xor_sync(0xffffffffu, ss, off);
        int gm = m0 + ty * 8 + i;
        float inv = 1.f / (sqrtf(ss) + 1e-13f);
        float mk  = masks[gm];                 // masks flattened [B*L] == row index
        float sc  = inv * mk;
        float o[8];
        #pragma unroll
        for (int j = 0; j < 8; j++) o[j] = acc[i][j] * sc;
        float* dst = C + (size_t)gm * CDIM + tx * 8;
        *(float4*)&dst[0] = *(const float4*)&o[0];
        *(float4*)&dst[4] = *(const float4*)&o[4];
    }
}

// ---------------- 4) matcher: sim GEMM + Gaussian-bin pooling ----------------
// 20 evenly spaced bins (mu = 0.95 - 0.1*(j-1), sigma=0.1) via recurrence:
//   g_1 = exp(-50 d0^2), t_1 = exp(-10 d0) * e^-0.5, g_{j+1} = g_j * t_j, t_{j+1} = t_j * e^-1
__device__ __forceinline__ void accum_bins(float* h, float s, float sel) {
    float d1 = s - 1.0f;
    h[0] += sel * __expf(-500000.f * d1 * d1);
    float d0 = s - 0.95f;
    float g = sel * __expf(-50.f * d0 * d0);
    float t = __expf(-10.f * d0) * 0.60653065971f;   // e^-0.5
    #pragma unroll
    for (int j = 1; j <= 20; j++) {
        h[j] += g;
        g *= t;
        t *= 0.36787944117f;                          // e^-1
    }
}

__global__ __launch_bounds__(256) void matcher_kernel(const float* __restrict__ qmasks) {
    const int b    = blockIdx.x;
    const int pair = blockIdx.y;          // qk*3 + dk
    const int qk   = pair / 3, dk = pair % 3;
    const float* Q = g_QENC + ((size_t)qk * MQ + b * QLEN) * CDIM;
    const float* D = g_DENC + ((size_t)dk * MD + b * DLEN) * CDIM;
    const int qlen_v = QLEN - qk;         // valid conv outputs = L - k + 1
    const int dlen_v = DLEN - dk;

    __shared__ float Qs[128][36];         // [k][q], padded for 16B-aligned float4 rows
    __shared__ float Ds[128][65];         // [k][d], pad 65 -> conflict-free lane reads
    __shared__ float warp_out[8][21];

    const int tid = threadIdx.x;
    const int tq  = tid >> 5;             // warp id: owns q cols tq*4 .. tq*4+3
    const int td  = tid & 31;             // lane: owns d rows td, td+32 of each tile

    // stage Q (32 rows x 128) transposed
    for (int i = tid; i < 32 * 32; i += 256) {
        int q = i >> 5, c4 = i & 31;
        float4 v = *(const float4*)(Q + (size_t)q * CDIM + c4 * 4);
        Qs[c4 * 4 + 0][q] = v.x;  Qs[c4 * 4 + 1][q] = v.y;
        Qs[c4 * 4 + 2][q] = v.z;  Qs[c4 * 4 + 3][q] = v.w;
    }

    float hist[4][21];
    #pragma unroll
    for (int qi = 0; qi < 4; qi++)
        #pragma unroll
        for (int j = 0; j < 21; j++) hist[qi][j] = 0.f;

    for (int dt = 0; dt < DLEN / 64; dt++) {
        __syncthreads();
        // stage D tile (64 rows x 128) transposed
        for (int i = tid; i < 64 * 32; i += 256) {
            int r = i >> 5, c4 = i & 31;
            float4 v = *(const float4*)(D + (size_t)(dt * 64 + r) * CDIM + c4 * 4);
            Ds[c4 * 4 + 0][r] = v.x;  Ds[c4 * 4 + 1][r] = v.y;
            Ds[c4 * 4 + 2][r] = v.z;  Ds[c4 * 4 + 3][r] = v.w;
        }
        __syncthreads();

        float s0[4] = {0.f, 0.f, 0.f, 0.f};
        float s1[4] = {0.f, 0.f, 0.f, 0.f};
        #pragma unroll 8
        for (int kk = 0; kk < 128; kk++) {
            float a0 = Ds[kk][td];
            float a1 = Ds[kk][td + 32];
            float4 bq = *(const float4*)&Qs[kk][tq * 4];
            s0[0] = fmaf(a0, bq.x, s0[0]);  s0[1] = fmaf(a0, bq.y, s0[1]);
            s0[2] = fmaf(a0, bq.z, s0[2]);  s0[3] = fmaf(a0, bq.w, s0[3]);
            s1[0] = fmaf(a1, bq.x, s1[0]);  s1[1] = fmaf(a1, bq.y, s1[1]);
            s1[2] = fmaf(a1, bq.z, s1[2]);  s1[3] = fmaf(a1, bq.w, s1[3]);
        }
        float sel0 = (dt * 64 + td      < dlen_v) ? 1.f : 0.f;
        float sel1 = (dt * 64 + td + 32 < dlen_v) ? 1.f : 0.f;
        #pragma unroll
        for (int qi = 0; qi < 4; qi++) {
            accum_bins(hist[qi], s0[qi], sel0);
            accum_bins(hist[qi], s1[qi], sel1);
        }
    }

    // warp reduce histograms (lanes cover all d rows)
    #pragma unroll
    for (int qi = 0; qi < 4; qi++)
        #pragma unroll
        for (int j = 0; j < 21; j++) {
            float v = hist[qi][j];
            #pragma unroll
            for (int off = 16; off > 0; off >>= 1)
                v += __shfl_down_sync(0xffffffffu, v, off);
            hist[qi][j] = v;
        }

    if (td == 0) {
        float part[21];
        #pragma unroll
        for (int j = 0; j < 21; j++) part[j] = 0.f;
        #pragma unroll
        for (int qi = 0; qi < 4; qi++) {
            int qrow = tq * 4 + qi;
            float w = (qrow < qlen_v) ? qmasks[b * QLEN + qrow] : 0.f;
            #pragma unroll
            for (int j = 0; j < 21; j++)
                part[j] += __logf(fmaxf(hist[qi][j], 1e-10f)) * 0.01f * w;
        }
        #pragma unroll
        for (int j = 0; j < 21; j++) warp_out[tq][j] = part[j];
    }
    __syncthreads();
    if (tid < 21) {
        float s = 0.f;
        #pragma unroll
        for (int w = 0; w < 8; w++) s += warp_out[w][tid];
        g_LOGITS[b * 189 + pair * 21 + tid] = s;
    }
}

// ---------------- 5) dense score + output assembly ----------------
__global__ void score_kernel(const float* __restrict__ dw, const float* __restrict__ db,
                             float* __restrict__ out, int out_size) {
    __shared__ float red[256];
    int b = blockIdx.x, tid = threadIdx.x;
    float v = (tid < 189) ? g_LOGITS[b * 189 + tid] * dw[tid] : 0.f;
    red[tid] = v;
    __syncthreads();
    for (int s = 128; s > 0; s >>= 1) {
        if (tid < s) red[tid] += red[tid + s];
        __syncthreads();
    }
    float score = red[0] + db[0];
    if (out_size >= B + B * 189) {                  // (score, logits) flattened
        if (tid == 0) out[b] = score;
        if (tid < 189) out[B + b * 189 + tid] = g_LOGITS[b * 189 + tid];
    } else if (out_size == B * 189) {               // logits only
        if (tid < 189) out[b * 189 + tid] = g_LOGITS[b * 189 + tid];
    } else {                                        // score only
        if (tid == 0 && b < out_size) out[b] = score;
    }
}

// ---------------- launch ----------------
extern "C" void kernel_launch(void* const* d_in, const int* in_sizes, int n_in,
                              void* d_out, int out_size) {
    const int*   qids   = (const int*)d_in[0];
    const float* qmask  = (const float*)d_in[1];
    const int*   dids   = (const int*)d_in[2];
    const float* dmask  = (const float*)d_in[3];
    const float* emb    = (const float*)d_in[4];
    const float* w1     = (const float*)d_in[5];
    const float* b1     = (const float*)d_in[6];
    const float* w2     = (const float*)d_in[7];
    const float* b2     = (const float*)d_in[8];
    const float* w3     = (const float*)d_in[9];
    const float* b3     = (const float*)d_in[10];
    const float* dw     = (const float*)d_in[11];
    const float* db     = (const float*)d_in[12];
    float* out = (float*)d_out;

    // 1) gather
    {
        int warps = MD + MQ + 8;
        int blocks = (warps * 32 + 255) / 256;
        gather_kernel<<<blocks, 256>>>(qids, dids, emb);
    }
    // 2) weight transpose
    wt_kernel<<<(1800 * CDIM + 255) / 256, 256>>>(w1, w2, w3);
    // 3) conv GEMMs (doc then query)
    conv_gemm_kernel<<<dim3(MD / 128, 3), 256>>>(0, b1, b2, b3, dmask);
    conv_gemm_kernel<<<dim3(MQ / 128, 3), 256>>>(1, b1, b2, b3, qmask);
    // 4) matchers: 32 batches x 9 pairs
    matcher_kernel<<<dim3(B, 9), 256>>>(qmask);
    // 5) score + output
    score_kernel<<<B, 256>>>(dw, db, out, out_size);
}

// round 6
// speedup vs baseline: 1.6340x; 1.6340x over previous
#include <cuda_runtime.h>
#include <cuda_bf16.h>
#include <cstdint>

#define B      32
#define QLEN   32
#define DLEN   1024
#define EMB    300
#define CDIM   128
#define MD     (B*DLEN)   // 32768 doc rows
#define MQ     (B*QLEN)   // 1024 query rows

// Row layout: [0,32768) doc, [32768,32896) zero pad, [32896,33920) query, [33920,33924) pad
#define QROW0   32896
#define NROWS   33924
#define KPAD    320        // K padded (300 -> 320) = 10 chunks of 32 f32
#define NCAT    768        // 6 tap-groups x 128 channels
#define MTILES  264        // 256 doc tiles + 8 query tiles

// ---------------- device scratch (zero-initialized globals) ----------------
__device__ float g_E[(size_t)NROWS * KPAD];       // gathered embeddings f32 (pad rows/cols 0)
__device__ float g_W[NCAT * KPAD];                // Wcat f32
__device__ float g_P[(size_t)NROWS * NCAT];       // partial conv outputs (pad rows stay 0)
__device__ float g_DENC[3ull * MD * CDIM];
__device__ float g_QENC[3ull * MQ * CDIM];
__device__ float g_LOGITS[B * 189];

__device__ __forceinline__ uint32_t smem_u32(const void* p) {
    uint32_t a;
    asm("{ .reg .u64 t; cvta.to.shared.u64 t, %1; cvt.u32.u64 %0, t; }" : "=r"(a) : "l"(p));
    return a;
}
__device__ __forceinline__ uint32_t f2tf32(float x) {
    uint32_t r;
    asm("cvt.rna.tf32.f32 %0, %1;" : "=r"(r) : "f"(x));
    return r;
}
__device__ __forceinline__ void ldmx4(uint32_t* r, uint32_t addr) {
    asm volatile("ldmatrix.sync.aligned.m8n8.x4.shared.b16 {%0,%1,%2,%3}, [%4];"
                 : "=r"(r[0]), "=r"(r[1]), "=r"(r[2]), "=r"(r[3]) : "r"(addr));
}
__device__ __forceinline__ void mma_tf32(float* c, const uint32_t* a, const uint32_t* b) {
    asm volatile("mma.sync.aligned.m16n8k8.row.col.f32.tf32.tf32.f32 "
                 "{%0,%1,%2,%3}, {%4,%5,%6,%7}, {%8,%9}, {%0,%1,%2,%3};"
                 : "+f"(c[0]), "+f"(c[1]), "+f"(c[2]), "+f"(c[3])
                 : "r"(a[0]), "r"(a[1]), "r"(a[2]), "r"(a[3]), "r"(b[0]), "r"(b[1]));
}

// ---------------- 1) gather embeddings -> padded f32 ----------------
__global__ void gather_kernel(const int* __restrict__ qids, const int* __restrict__ dids,
                              const float* __restrict__ emb) {
    int w = (blockIdx.x * blockDim.x + threadIdx.x) >> 5;
    int lane = threadIdx.x & 31;
    if (w >= MD + MQ) return;
    int id, drow;
    if (w < MD) { id = dids[w]; drow = w; }
    else        { id = qids[w - MD]; drow = QROW0 + (w - MD); }
    const float4* src = (const float4*)(emb + (size_t)id * EMB);
    float4* dst = (float4*)(g_E + (size_t)drow * KPAD);
    #pragma unroll
    for (int i = 0; i < 3; i++) {
        int c = lane + i * 32;                 // 80 float4 per row
        if (c < 80) dst[c] = (c < 75) ? src[c] : make_float4(0.f, 0.f, 0.f, 0.f);
    }
}

// ---------------- 2) Wcat (768 x 320) f32 ----------------
// group g: 0=(k1,t0) 1=(k2,t0) 2=(k2,t1) 3=(k3,t0) 4=(k3,t1) 5=(k3,t2)
__global__ void wcat_kernel(const float* __restrict__ w1, const float* __restrict__ w2,
                            const float* __restrict__ w3) {
    int idx = blockIdx.x * blockDim.x + threadIdx.x;
    if (idx >= NCAT * KPAD) return;
    int j = idx / KPAD, e = idx % KPAD;
    int g = j >> 7, c = j & 127;
    float v = 0.f;
    if (e < EMB) {
        if (g == 0)      v = w1[c * EMB + e];
        else if (g == 1) v = w2[(c * EMB + e) * 2 + 0];
        else if (g == 2) v = w2[(c * EMB + e) * 2 + 1];
        else             v = w3[(c * EMB + e) * 3 + (g - 3)];
    }
    g_W[idx] = v;
}

// ---------------- 3) TF32-split MMA GEMM: P[128 x 128] per CTA ----------------
// grid (6, 264): x = N pass, y = M tile. K chunks of 32 f32, double-buffered.
// smem per stage: Ah, Al, Bh, Bl each 128 rows x 32 f32, row stride 36 f32 (144 B).
#define STRIDE_B  144
#define TILE_B    (128 * STRIDE_B)       // 18432
#define STAGE_B   (4 * TILE_B)           // 73728
#define SMEM_DYN  (2 * STAGE_B)          // 147456

__global__ void __launch_bounds__(256, 1) conv_tf32_kernel() {
    extern __shared__ char sm[];
    const int mt = blockIdx.y, pass = blockIdx.x;
    const int mbase = (mt < 256) ? mt * 128 : QROW0 + (mt - 256) * 128;
    const int jbase = pass * 128;
    const int tid = threadIdx.x, wid = tid >> 5, lane = tid & 31;
    const int wm = wid & 1, wn = wid >> 1;     // warp tile: rows wm*64, cols wn*32

    const float* Asrc = g_E + (size_t)mbase * KPAD;
    const float* Bsrc = g_W + (size_t)jbase * KPAD;
    const uint32_t smb = smem_u32(sm);

    const int lr = tid >> 1, lh = tid & 1;     // loader: row, 16-f32 half

    float4 ldA[4], ldB[4];
    auto gload = [&](int kc) {
        const float* pa = Asrc + (size_t)lr * KPAD + kc * 32 + lh * 16;
        const float* pb = Bsrc + (size_t)lr * KPAD + kc * 32 + lh * 16;
        #pragma unroll
        for (int i = 0; i < 4; i++) {
            ldA[i] = *(const float4*)(pa + i * 4);
            ldB[i] = *(const float4*)(pb + i * 4);
        }
    };
    auto split_store = [&](int s) {
        char* st = sm + s * STAGE_B;
        uint32_t off = (uint32_t)lr * STRIDE_B + lh * 64;
        #pragma unroll
        for (int i = 0; i < 4; i++) {
            float4 x = ldA[i];
            uint4 hi, lo;
            hi.x = f2tf32(x.x); lo.x = f2tf32(x.x - __uint_as_float(hi.x));
            hi.y = f2tf32(x.y); lo.y = f2tf32(x.y - __uint_as_float(hi.y));
            hi.z = f2tf32(x.z); lo.z = f2tf32(x.z - __uint_as_float(hi.z));
            hi.w = f2tf32(x.w); lo.w = f2tf32(x.w - __uint_as_float(hi.w));
            *(uint4*)(st + off + i * 16)          = hi;   // Ah
            *(uint4*)(st + TILE_B + off + i * 16) = lo;   // Al
            x = ldB[i];
            hi.x = f2tf32(x.x); lo.x = f2tf32(x.x - __uint_as_float(hi.x));
            hi.y = f2tf32(x.y); lo.y = f2tf32(x.y - __uint_as_float(hi.y));
            hi.z = f2tf32(x.z); lo.z = f2tf32(x.z - __uint_as_float(hi.z));
            hi.w = f2tf32(x.w); lo.w = f2tf32(x.w - __uint_as_float(hi.w));
            *(uint4*)(st + 2 * TILE_B + off + i * 16) = hi;   // Bh
            *(uint4*)(st + 3 * TILE_B + off + i * 16) = lo;   // Bl
        }
    };

    float acc[4][4][4];
    #pragma unroll
    for (int i = 0; i < 4; i++)
        #pragma unroll
        for (int j = 0; j < 4; j++)
            #pragma unroll
            for (int k = 0; k < 4; k++) acc[i][j][k] = 0.f;

    // ldmatrix lane address components (fp32-as-b16 pairs trick)
    const int lg = lane >> 3, lj = lane & 7;
    // A x4: m0=(r0-7,k0-3) m1=(r8-15,k0-3) m2=(r0-7,k4-7) m3=(r8-15,k4-7)
    const uint32_t a_off = (uint32_t)(lj + 8 * (lg & 1)) * STRIDE_B + (uint32_t)(lg >> 1) * 16;
    // B x4: m0=(n0-7,k0-3) m1=(n0-7,k4-7) m2=(n8-15,k0-3) m3=(n8-15,k4-7)
    const uint32_t b_off = (uint32_t)(lj + 8 * (lg >> 1)) * STRIDE_B + (uint32_t)(lg & 1) * 16;

    gload(0);
    split_store(0);
    __syncthreads();

    for (int kc = 0; kc < 10; kc++) {
        if (kc < 9) gload(kc + 1);
        const int s = kc & 1;
        const uint32_t Ah = smb + s * STAGE_B;
        const uint32_t Al = Ah + TILE_B;
        const uint32_t Bh = Ah + 2 * TILE_B;
        const uint32_t Bl = Ah + 3 * TILE_B;

        #pragma unroll
        for (int ks = 0; ks < 4; ks++) {
            const uint32_t kb = ks * 32;       // 8 f32 = 32 B per k-step
            uint32_t bh[4][2], bl[4][2];
            #pragma unroll
            for (int h = 0; h < 2; h++) {
                uint32_t off = (uint32_t)(wn * 32 + h * 16) * STRIDE_B + kb + b_off;
                uint32_t r[4];
                ldmx4(r, Bh + off);
                bh[h * 2 + 0][0] = r[0]; bh[h * 2 + 0][1] = r[1];
                bh[h * 2 + 1][0] = r[2]; bh[h * 2 + 1][1] = r[3];
                ldmx4(r, Bl + off);
                bl[h * 2 + 0][0] = r[0]; bl[h * 2 + 0][1] = r[1];
                bl[h * 2 + 1][0] = r[2]; bl[h * 2 + 1][1] = r[3];
            }
            #pragma unroll
            for (int mf = 0; mf < 4; mf++) {
                uint32_t off = (uint32_t)(wm * 64 + mf * 16) * STRIDE_B + kb + a_off;
                uint32_t ah[4], al[4];
                ldmx4(ah, Ah + off);
                ldmx4(al, Al + off);
                #pragma unroll
                for (int nf = 0; nf < 4; nf++) {
                    mma_tf32(acc[mf][nf], ah, bh[nf]);
                    mma_tf32(acc[mf][nf], al, bh[nf]);
                    mma_tf32(acc[mf][nf], ah, bl[nf]);
                }
            }
        }
        __syncthreads();
        if (kc < 9) {
            split_store(s ^ 1);
            __syncthreads();
        }
    }

    // epilogue: write P  (c0,c1 -> row; c2,c3 -> row+8)
    const int r0 = lane >> 2, c0 = (lane & 3) * 2;
    #pragma unroll
    for (int mf = 0; mf < 4; mf++) {
        int row = mbase + wm * 64 + mf * 16 + r0;
        #pragma unroll
        for (int nf = 0; nf < 4; nf++) {
            int col = jbase + wn * 32 + nf * 8 + c0;
            float* p = g_P + (size_t)row * NCAT + col;
            *(float2*)p                      = make_float2(acc[mf][nf][0], acc[mf][nf][1]);
            *(float2*)(p + (size_t)8 * NCAT) = make_float2(acc[mf][nf][2], acc[mf][nf][3]);
        }
    }
}

// ---------------- 4) combine taps + bias + relu + L2 normalize + mask ----------------
__global__ void combine_kernel(const float* __restrict__ b1, const float* __restrict__ b2,
                               const float* __restrict__ b3,
                               const float* __restrict__ qmask, const float* __restrict__ dmask) {
    int w = (blockIdx.x * blockDim.x + threadIdx.x) >> 5;
    int lane = threadIdx.x & 31;
    if (w >= (MD + MQ) * 3) return;
    int kidx = w % 3;
    int row  = w / 3;
    int prow; float* out; float mk;
    if (row < MD) { prow = row; out = g_DENC + ((size_t)kidx * MD + row) * CDIM; mk = dmask[row]; }
    else {
        int q = row - MD;
        prow = QROW0 + q;
        out = g_QENC + ((size_t)kidx * MQ + q) * CDIM;
        mk = qmask[q];
    }
    const float* bias = (kidx == 0) ? b1 : (kidx == 1 ? b2 : b3);
    const float* P0 = g_P + (size_t)prow * NCAT;
    int c = lane * 4;
    float4 v;
    if (kidx == 0) {
        v = *(const float4*)(P0 + c);
    } else if (kidx == 1) {
        float4 a = *(const float4*)(P0 + 128 + c);
        float4 b = *(const float4*)(P0 + NCAT + 256 + c);
        v = make_float4(a.x + b.x, a.y + b.y, a.z + b.z, a.w + b.w);
    } else {
        float4 a = *(const float4*)(P0 + 384 + c);
        float4 b = *(const float4*)(P0 + NCAT + 512 + c);
        float4 d = *(const float4*)(P0 + 2 * NCAT + 640 + c);
        v = make_float4(a.x + b.x + d.x, a.y + b.y + d.y, a.z + b.z + d.z, a.w + b.w + d.w);
    }
    float4 bv = *(const float4*)(bias + c);
    v.x = fmaxf(v.x + bv.x, 0.f);  v.y = fmaxf(v.y + bv.y, 0.f);
    v.z = fmaxf(v.z + bv.z, 0.f);  v.w = fmaxf(v.w + bv.w, 0.f);
    float ss = v.x * v.x + v.y * v.y + v.z * v.z + v.w * v.w;
    #pragma unroll
    for (int off = 16; off > 0; off >>= 1)
        ss += __shfl_xor_sync(0xffffffffu, ss, off);
    float sc = mk / (sqrtf(ss) + 1e-13f);
    v.x *= sc; v.y *= sc; v.z *= sc; v.w *= sc;
    *(float4*)(out + c) = v;
}

// ---------------- 5) matcher: sim GEMM + Gaussian-bin pooling ----------------
__device__ __forceinline__ void accum_bins(float* h, float s, float sel) {
    float d1 = s - 1.0f;
    h[0] += sel * __expf(-500000.f * d1 * d1);
    float d0 = s - 0.95f;
    float g = sel * __expf(-50.f * d0 * d0);
    float t = __expf(-10.f * d0) * 0.60653065971f;
    #pragma unroll
    for (int j = 1; j <= 20; j++) {
        h[j] += g;
        g *= t;
        t *= 0.36787944117f;
    }
}

__global__ __launch_bounds__(256) void matcher_kernel(const float* __restrict__ qmasks) {
    const int b    = blockIdx.x;
    const int pair = blockIdx.y;
    const int qk   = pair / 3, dk = pair % 3;
    const float* Q = g_QENC + ((size_t)qk * MQ + b * QLEN) * CDIM;
    const float* D = g_DENC + ((size_t)dk * MD + b * DLEN) * CDIM;
    const int qlen_v = QLEN - qk;
    const int dlen_v = DLEN - dk;

    __shared__ float Qs[128][36];
    __shared__ float Ds[128][65];
    __shared__ float warp_out[8][21];

    const int tid = threadIdx.x;
    const int tq  = tid >> 5;
    const int td  = tid & 31;

    for (int i = tid; i < 32 * 32; i += 256) {
        int q = i >> 5, c4 = i & 31;
        float4 v = *(const float4*)(Q + (size_t)q * CDIM + c4 * 4);
        Qs[c4 * 4 + 0][q] = v.x;  Qs[c4 * 4 + 1][q] = v.y;
        Qs[c4 * 4 + 2][q] = v.z;  Qs[c4 * 4 + 3][q] = v.w;
    }

    float hist[4][21];
    #pragma unroll
    for (int qi = 0; qi < 4; qi++)
        #pragma unroll
        for (int j = 0; j < 21; j++) hist[qi][j] = 0.f;

    for (int dt = 0; dt < DLEN / 64; dt++) {
        __syncthreads();
        for (int i = tid; i < 64 * 32; i += 256) {
            int r = i >> 5, c4 = i & 31;
            float4 v = *(const float4*)(D + (size_t)(dt * 64 + r) * CDIM + c4 * 4);
            Ds[c4 * 4 + 0][r] = v.x;  Ds[c4 * 4 + 1][r] = v.y;
            Ds[c4 * 4 + 2][r] = v.z;  Ds[c4 * 4 + 3][r] = v.w;
        }
        __syncthreads();

        float s0[4] = {0.f, 0.f, 0.f, 0.f};
        float s1[4] = {0.f, 0.f, 0.f, 0.f};
        #pragma unroll 8
        for (int kk = 0; kk < 128; kk++) {
            float a0 = Ds[kk][td];
            float a1 = Ds[kk][td + 32];
            float4 bq = *(const float4*)&Qs[kk][tq * 4];
            s0[0] = fmaf(a0, bq.x, s0[0]);  s0[1] = fmaf(a0, bq.y, s0[1]);
            s0[2] = fmaf(a0, bq.z, s0[2]);  s0[3] = fmaf(a0, bq.w, s0[3]);
            s1[0] = fmaf(a1, bq.x, s1[0]);  s1[1] = fmaf(a1, bq.y, s1[1]);
            s1[2] = fmaf(a1, bq.z, s1[2]);  s1[3] = fmaf(a1, bq.w, s1[3]);
        }
        float sel0 = (dt * 64 + td      < dlen_v) ? 1.f : 0.f;
        float sel1 = (dt * 64 + td + 32 < dlen_v) ? 1.f : 0.f;
        #pragma unroll
        for (int qi = 0; qi < 4; qi++) {
            accum_bins(hist[qi], s0[qi], sel0);
            accum_bins(hist[qi], s1[qi], sel1);
        }
    }

    #pragma unroll
    for (int qi = 0; qi < 4; qi++)
        #pragma unroll
        for (int j = 0; j < 21; j++) {
            float v = hist[qi][j];
            #pragma unroll
            for (int off = 16; off > 0; off >>= 1)
                v += __shfl_down_sync(0xffffffffu, v, off);
            hist[qi][j] = v;
        }

    if (td == 0) {
        float part[21];
        #pragma unroll
        for (int j = 0; j < 21; j++) part[j] = 0.f;
        #pragma unroll
        for (int qi = 0; qi < 4; qi++) {
            int qrow = tq * 4 + qi;
            float w = (qrow < qlen_v) ? qmasks[b * QLEN + qrow] : 0.f;
            #pragma unroll
            for (int j = 0; j < 21; j++)
                part[j] += __logf(fmaxf(hist[qi][j], 1e-10f)) * 0.01f * w;
        }
        #pragma unroll
        for (int j = 0; j < 21; j++) warp_out[tq][j] = part[j];
    }
    __syncthreads();
    if (tid < 21) {
        float s = 0.f;
        #pragma unroll
        for (int w = 0; w < 8; w++) s += warp_out[w][tid];
        g_LOGITS[b * 189 + pair * 21 + tid] = s;
    }
}

// ---------------- 6) dense score + output ----------------
__global__ void score_kernel(const float* __restrict__ dw, const float* __restrict__ db,
                             float* __restrict__ out, int out_size) {
    __shared__ float red[256];
    int b = blockIdx.x, tid = threadIdx.x;
    float v = (tid < 189) ? g_LOGITS[b * 189 + tid] * dw[tid] : 0.f;
    red[tid] = v;
    __syncthreads();
    for (int s = 128; s > 0; s >>= 1) {
        if (tid < s) red[tid] += red[tid + s];
        __syncthreads();
    }
    float score = red[0] + db[0];
    if (out_size >= B + B * 189) {
        if (tid == 0) out[b] = score;
        if (tid < 189) out[B + b * 189 + tid] = g_LOGITS[b * 189 + tid];
    } else if (out_size == B * 189) {
        if (tid < 189) out[b * 189 + tid] = g_LOGITS[b * 189 + tid];
    } else {
        if (tid == 0 && b < out_size) out[b] = score;
    }
}

// ---------------- launch ----------------
extern "C" void kernel_launch(void* const* d_in, const int* in_sizes, int n_in,
                              void* d_out, int out_size) {
    const int*   qids   = (const int*)d_in[0];
    const float* qmask  = (const float*)d_in[1];
    const int*   dids   = (const int*)d_in[2];
    const float* dmask  = (const float*)d_in[3];
    const float* emb    = (const float*)d_in[4];
    const float* w1     = (const float*)d_in[5];
    const float* b1     = (const float*)d_in[6];
    const float* w2     = (const float*)d_in[7];
    const float* b2     = (const float*)d_in[8];
    const float* w3     = (const float*)d_in[9];
    const float* b3     = (const float*)d_in[10];
    const float* dw     = (const float*)d_in[11];
    const float* db     = (const float*)d_in[12];
    float* out = (float*)d_out;

    cudaFuncSetAttribute(conv_tf32_kernel, cudaFuncAttributeMaxDynamicSharedMemorySize, SMEM_DYN);

    gather_kernel<<<((MD + MQ) * 32 + 255) / 256, 256>>>(qids, dids, emb);
    wcat_kernel<<<(NCAT * KPAD + 255) / 256, 256>>>(w1, w2, w3);
    conv_tf32_kernel<<<dim3(6, MTILES), 256, SMEM_DYN>>>();
    combine_kernel<<<((MD + MQ) * 3 * 32 + 255) / 256, 256>>>(b1, b2, b3, qmask, dmask);
    matcher_kernel<<<dim3(B, 9), 256>>>(qmask);
    score_kernel<<<B, 256>>>(dw, db, out, out_size);
}